// round 15
// baseline (speedup 1.0000x reference)
#include <cuda_runtime.h>
#include <cuda_bf16.h>
#include <stdint.h>

#define N_NODES   10000
#define N_EDGES   160000
#define F_IN      512
#define H_FEATS   512
#define N_CLASSES 128
#define PKA       (F_IN / 2)     // 256 pairs per activation row
#define PKW2      512            // pairs per W2 row (K=1024)

// ---------------------------------------------------------------------------
// Device scratch (BSS zero-init; g_cnt/g_cur re-zeroed by tail kernel)
// ---------------------------------------------------------------------------
__device__ int   g_cnt[N_NODES];
__device__ int   g_cur[N_NODES];
__device__ int   g_off[N_NODES + 1];
__device__ int   g_adj[N_EDGES];
__device__ float g_U  [(size_t)N_NODES * H_FEATS];   // h @ W1_top
__device__ float g_V  [(size_t)N_NODES * H_FEATS];   // h @ W1_bot
__device__ float g_Y2 [(size_t)N_NODES * N_CLASSES];
__device__ float g_P2 [(size_t)N_NODES * N_CLASSES];
__device__ uint32_t g_hPh [(size_t)N_NODES * PKA];
__device__ uint32_t g_hPl [(size_t)N_NODES * PKA];
__device__ uint32_t g_h1Ph[(size_t)N_NODES * PKA];
__device__ uint32_t g_h1Pl[(size_t)N_NODES * PKA];
__device__ uint32_t g_W1ph[(size_t)1024 * PKA];
__device__ uint32_t g_W1pl[(size_t)1024 * PKA];
__device__ uint32_t g_W2ph[(size_t)N_CLASSES * PKW2];
__device__ uint32_t g_W2pl[(size_t)N_CLASSES * PKW2];

// ---------------------------------------------------------------------------
// helpers
// ---------------------------------------------------------------------------
__device__ __forceinline__ void cp_async16(uint32_t dst, const void* src, int src_bytes) {
    asm volatile("cp.async.cg.shared.global [%0], [%1], 16, %2;"
                 :: "r"(dst), "l"(src), "r"(src_bytes));
}
__device__ __forceinline__ void cp_commit() {
    asm volatile("cp.async.commit_group;" ::: "memory");
}
template <int N>
__device__ __forceinline__ void cp_wait() {
    asm volatile("cp.async.wait_group %0;" :: "n"(N) : "memory");
}
__device__ __forceinline__ void mma_bf16(float* c, const uint32_t* a, const uint32_t* b) {
    asm volatile(
        "mma.sync.aligned.m16n8k16.row.col.f32.bf16.bf16.f32 "
        "{%0,%1,%2,%3}, {%4,%5,%6,%7}, {%8,%9}, {%0,%1,%2,%3};"
        : "+f"(c[0]), "+f"(c[1]), "+f"(c[2]), "+f"(c[3])
        : "r"(a[0]), "r"(a[1]), "r"(a[2]), "r"(a[3]), "r"(b[0]), "r"(b[1]));
}
__device__ __forceinline__ void ldsm_x4(uint32_t& r0, uint32_t& r1, uint32_t& r2, uint32_t& r3,
                                        uint32_t addr) {
    asm volatile("ldmatrix.sync.aligned.m8n8.x4.shared.b16 {%0,%1,%2,%3}, [%4];"
                 : "=r"(r0), "=r"(r1), "=r"(r2), "=r"(r3) : "r"(addr));
}
__device__ __forceinline__ uint32_t pack_bf16x2(float x0, float x1) {
    uint32_t r;
    asm("cvt.rn.bf16x2.f32 %0, %1, %2;" : "=r"(r) : "f"(x1), "f"(x0));
    return r;
}
__device__ __forceinline__ void split2_bf16(float x0, float x1, uint32_t& hi, uint32_t& lo) {
    hi = pack_bf16x2(x0, x1);
    float h0 = __uint_as_float(hi << 16);
    float h1 = __uint_as_float(hi & 0xFFFF0000u);
    lo = pack_bf16x2(x0 - h0, x1 - h1);
}

// ---------------------------------------------------------------------------
// CSR build
// ---------------------------------------------------------------------------
__global__ void count_kernel(const int* __restrict__ dst) {
    int e = blockIdx.x * blockDim.x + threadIdx.x;
    if (e < N_EDGES) atomicAdd(&g_cnt[dst[e]], 1);
}
__global__ void scan_kernel() {
    __shared__ int wsum[32];
    __shared__ int chunk_total;
    const int lane = threadIdx.x & 31;
    const int wid  = threadIdx.x >> 5;
    int running = 0;
    for (int base = 0; base < N_NODES; base += 1024) {
        int i = base + threadIdx.x;
        int v = (i < N_NODES) ? g_cnt[i] : 0;
        int s = v;
        #pragma unroll
        for (int o = 1; o < 32; o <<= 1) {
            int u = __shfl_up_sync(0xffffffffu, s, o);
            if (lane >= o) s += u;
        }
        if (lane == 31) wsum[wid] = s;
        __syncthreads();
        if (wid == 0) {
            int ws = wsum[lane];
            #pragma unroll
            for (int o = 1; o < 32; o <<= 1) {
                int u = __shfl_up_sync(0xffffffffu, ws, o);
                if (lane >= o) ws += u;
            }
            wsum[lane] = ws;
            if (lane == 31) chunk_total = ws;
        }
        __syncthreads();
        int wpref = (wid > 0) ? wsum[wid - 1] : 0;
        if (i < N_NODES) g_off[i] = running + wpref + s - v;
        running += chunk_total;
        __syncthreads();
    }
    if (threadIdx.x == 0) g_off[N_NODES] = running;
}
__global__ void fill_kernel(const int* __restrict__ src, const int* __restrict__ dst) {
    int e = blockIdx.x * blockDim.x + threadIdx.x;
    if (e < N_EDGES) {
        int d = dst[e];
        int p = atomicAdd(&g_cur[d], 1);
        g_adj[g_off[d] + p] = src[e];
    }
}

// ---------------------------------------------------------------------------
// pack_all: W1 (fused-B layout), W2, and h, one launch.
// ---------------------------------------------------------------------------
__global__ void pack_all_kernel(const float* __restrict__ W1,
                                const float* __restrict__ W2,
                                const float* __restrict__ h) {
    __shared__ float sh[64][33];
    const int tx = threadIdx.x, ty = threadIdx.y;
    const int tid = ty * 32 + tx;

    if (blockIdx.x >= 36) {
        int chunk = (blockIdx.x - 36) * 16 + blockIdx.y;
        int base = chunk * 4000;
        const float2* h2 = (const float2*)h;
        for (int i = tid; i < 4000; i += 256) {
            int p = base + i;
            float2 v = h2[p];
            uint32_t hi, lo;
            split2_bf16(v.x, v.y, hi, lo);
            g_hPh[p] = hi;
            g_hPl[p] = lo;
        }
        return;
    }

    const bool isW1 = (blockIdx.x < 32);
    if (isW1 && blockIdx.y >= 8) return;

    const float* W;
    uint32_t *Wph, *Wpl;
    int srcRow0, srcCol0, srcLd, n0, ldP;
    int k0 = blockIdx.y * 64;
    if (isW1) {
        n0 = blockIdx.x * 32;
        srcRow0 = k0 + (n0 >= 512 ? 512 : 0);
        srcCol0 = n0 & 511;
        srcLd = 512;
        W = W1; Wph = g_W1ph; Wpl = g_W1pl; ldP = PKA;
    } else {
        n0 = (blockIdx.x - 32) * 32;
        srcRow0 = k0;
        srcCol0 = n0;
        srcLd = 128;
        W = W2; Wph = g_W2ph; Wpl = g_W2pl; ldP = PKW2;
    }

    #pragma unroll
    for (int j = 0; j < 64; j += 8)
        sh[j + ty][tx] = W[(size_t)(srcRow0 + j + ty) * srcLd + srcCol0 + tx];
    __syncthreads();
    #pragma unroll
    for (int j = 0; j < 32; j += 8) {
        int nl = ty + j;
        float x0 = sh[2 * tx][nl];
        float x1 = sh[2 * tx + 1][nl];
        uint32_t hi, lo;
        split2_bf16(x0, x1, hi, lo);
        size_t o = (size_t)(n0 + nl) * ldP + (k0 >> 1) + tx;
        Wph[o] = hi;
        Wpl[o] = lo;
    }
}

// ---------------------------------------------------------------------------
// Fused layer-1 tail: h1 = relu(U[n] + mean V[neigh] + b1), packed out.
// ---------------------------------------------------------------------------
__global__ void agg_relu_pack_kernel(const float* __restrict__ b1) {
    int n   = blockIdx.x;
    int st  = g_off[n];
    int deg = g_off[n + 1] - st;
    int c4  = threadIdx.x;

    float4 acc = make_float4(0.f, 0.f, 0.f, 0.f);
    int e = 0;
    for (; e + 1 < deg; e += 2) {
        int s0 = g_adj[st + e];
        int s1 = g_adj[st + e + 1];
        float4 v0 = *(const float4*)(g_V + (size_t)s0 * 512 + c4 * 4);
        float4 v1 = *(const float4*)(g_V + (size_t)s1 * 512 + c4 * 4);
        acc.x += v0.x + v1.x; acc.y += v0.y + v1.y;
        acc.z += v0.z + v1.z; acc.w += v0.w + v1.w;
    }
    if (e < deg) {
        int s0 = g_adj[st + e];
        float4 v0 = *(const float4*)(g_V + (size_t)s0 * 512 + c4 * 4);
        acc.x += v0.x; acc.y += v0.y; acc.z += v0.z; acc.w += v0.w;
    }
    float inv = (deg > 0) ? (1.0f / (float)deg) : 0.0f;
    float4 u = *(const float4*)(g_U + (size_t)n * 512 + c4 * 4);
    float4 b = *(const float4*)(b1 + c4 * 4);
    float v0 = fmaxf(u.x + acc.x * inv + b.x, 0.f);
    float v1 = fmaxf(u.y + acc.y * inv + b.y, 0.f);
    float v2 = fmaxf(u.z + acc.z * inv + b.z, 0.f);
    float v3 = fmaxf(u.w + acc.w * inv + b.w, 0.f);
    uint32_t h0, l0, h1, l1;
    split2_bf16(v0, v1, h0, l0);
    split2_bf16(v2, v3, h1, l1);
    ((uint2*)(g_h1Ph + (size_t)n * PKA))[c4] = make_uint2(h0, h1);
    ((uint2*)(g_h1Pl + (size_t)n * PKA))[c4] = make_uint2(l0, l1);
}

// out[n] = P2[n] + mean Y2[neigh]; re-zero cnt/cur for next call
__global__ void agg128_final_kernel(float* __restrict__ out) {
    int gi = blockIdx.x * blockDim.x + threadIdx.x;
    if (gi < N_NODES) { g_cnt[gi] = 0; g_cur[gi] = 0; }

    int n = blockIdx.x * 4 + (threadIdx.x >> 5);
    int lane = threadIdx.x & 31;
    if (n >= N_NODES) return;
    int st  = g_off[n];
    int deg = g_off[n + 1] - st;
    float4 acc = make_float4(0.f, 0.f, 0.f, 0.f);
    int e = 0;
    for (; e + 1 < deg; e += 2) {
        int s0 = g_adj[st + e];
        int s1 = g_adj[st + e + 1];
        float4 v0 = *(const float4*)(g_Y2 + (size_t)s0 * 128 + lane * 4);
        float4 v1 = *(const float4*)(g_Y2 + (size_t)s1 * 128 + lane * 4);
        acc.x += v0.x + v1.x; acc.y += v0.y + v1.y;
        acc.z += v0.z + v1.z; acc.w += v0.w + v1.w;
    }
    if (e < deg) {
        int s0 = g_adj[st + e];
        float4 v0 = *(const float4*)(g_Y2 + (size_t)s0 * 128 + lane * 4);
        acc.x += v0.x; acc.y += v0.y; acc.z += v0.z; acc.w += v0.w;
    }
    float inv = (deg > 0) ? (1.0f / (float)deg) : 0.0f;
    float4 p = *(const float4*)(g_P2 + (size_t)n * 128 + lane * 4);
    acc.x = acc.x * inv + p.x; acc.y = acc.y * inv + p.y;
    acc.z = acc.z * inv + p.z; acc.w = acc.w * inv + p.w;
    *(float4*)(out + (size_t)n * 128 + lane * 4) = acc;
}

// ---------------------------------------------------------------------------
// bf16x3 GEMM with ldmatrix fragment loads.
// K=512 (16 stages of BK=32). MODE 0 (NT=4): split-UV. MODE 1 (NT=8): dual.
// SMEM per stage: AH[128][20] AL BH[BN][20] BL (uint32 words), stride-20
// conflict-free for ldmatrix (8 rows x 16B land on disjoint bank quads).
// ---------------------------------------------------------------------------
#define TSTR 20
#define A_SEG (128 * TSTR)
#define NSTAGES 16

template <int NT, int MODE>
__device__ __forceinline__ void gemm_body(
        const uint32_t* __restrict__ AH, const uint32_t* __restrict__ AL,
        const uint32_t* __restrict__ Wph, const uint32_t* __restrict__ Wpl, int ldP,
        const float* __restrict__ bias,
        float* __restrict__ D0, float* __restrict__ D1,
        int M, int koffp0, int koffp1) {
    extern __shared__ uint32_t smem[];

    constexpr int BN    = 16 * NT;
    constexpr int B_SEG = BN * TSTR;
    constexpr int STAGE_W = 2 * A_SEG + 2 * B_SEG;
    constexpr int NTQ   = NT / 2;

    const int t     = threadIdx.x;
    const int lane  = t & 31;
    const int wid   = t >> 5;
    const int warpM = wid & 3;
    const int warpN = wid >> 2;
    const int gid   = lane >> 2;
    const int tig   = lane & 3;
    const int m0    = blockIdx.y * 128;

    int n0, koffp;
    float* D = D0;
    const float* biasp = nullptr;
    if (MODE == 0) {
        n0 = blockIdx.x * BN;
        koffp = koffp0;
    } else {
        n0 = 0;
        if (blockIdx.x == 0) { D = D0; koffp = koffp0; }
        else                 { D = D1; koffp = koffp1; biasp = bias; }
    }

    // cp.async loaders
    const int lrow  = t >> 1;
    const int lhw   = (t & 1) * 8;
    const int aRow  = m0 + lrow;
    const int aOK   = (aRow < M) ? 16 : 0;
    const int aRowC = (aRow < M) ? aRow : 0;
    const int bRow = (NT == 8) ? (t >> 1) : (t >> 2);
    const int bW   = (NT == 8) ? ((t & 1) * 8) : ((t & 3) * 4);
    const uint32_t* WphRow = Wph + (size_t)(n0 + bRow) * ldP + koffp;
    const uint32_t* WplRow = Wpl + (size_t)(n0 + bRow) * ldP + koffp;

    float acc[2][NT][4];
    #pragma unroll
    for (int mt = 0; mt < 2; mt++)
        #pragma unroll
        for (int nt = 0; nt < NT; nt++)
            #pragma unroll
            for (int q = 0; q < 4; q++) acc[mt][nt][q] = 0.f;

    const uint32_t smemBase = (uint32_t)__cvta_generic_to_shared(smem);
    const uint32_t aOfs = (uint32_t)(lrow * TSTR + lhw) * 4;
    const uint32_t bOfs = (uint32_t)(bRow * TSTR + bW) * 4;

    // ldmatrix lane mapping: row = base + (l&7) + ((l>>3)&1)*8, chunk = l>>4
    const int lmRow   = (lane & 7) + ((lane >> 3) & 1) * 8;
    const int lmChunk = (lane >> 4) * 4;     // word offset of 16B chunk
    // A base word offsets for mt=0,1 (w term added in loop)
    const uint32_t lmA0 = (uint32_t)((warpM * 32 + lmRow) * TSTR + lmChunk) * 4;
    const uint32_t lmA1 = lmA0 + (uint32_t)(16 * TSTR) * 4;
    // B base word offsets for ntq (16 n-rows each)
    const uint32_t lmB0 = (uint32_t)((warpN * (NT * 8) + lmRow) * TSTR + lmChunk) * 4;

    auto load_stage = [&](int s, int bf) {
        uint32_t stB = smemBase + (uint32_t)(bf * STAGE_W) * 4;
        const int pb = s * 16;
        const uint32_t* ah = AH + (size_t)aRowC * PKA + pb + lhw;
        const uint32_t* al = AL + (size_t)aRowC * PKA + pb + lhw;
        cp_async16(stB + aOfs,                  ah,     aOK);
        cp_async16(stB + aOfs + 16,             ah + 4, aOK);
        cp_async16(stB + A_SEG * 4 + aOfs,      al,     aOK);
        cp_async16(stB + A_SEG * 4 + aOfs + 16, al + 4, aOK);
        uint32_t bhB = stB + 2 * A_SEG * 4 + bOfs;
        uint32_t blB = bhB + B_SEG * 4;
        const uint32_t* bh = WphRow + pb + bW;
        const uint32_t* bl = WplRow + pb + bW;
        if (NT == 8) {
            cp_async16(bhB,      bh,     16);
            cp_async16(bhB + 16, bh + 4, 16);
            cp_async16(blB,      bl,     16);
            cp_async16(blB + 16, bl + 4, 16);
        } else {
            cp_async16(bhB, bh, 16);
            cp_async16(blB, bl, 16);
        }
    };

    load_stage(0, 0);
    cp_commit();

    for (int s = 0; s < NSTAGES; s++) {
        const int bf = s & 1;
        if (s + 1 < NSTAGES) { load_stage(s + 1, bf ^ 1); cp_commit(); cp_wait<1>(); }
        else                 { cp_wait<0>(); }
        __syncthreads();

        const uint32_t stAH = smemBase + (uint32_t)(bf * STAGE_W) * 4;
        const uint32_t stAL = stAH + (uint32_t)A_SEG * 4;
        const uint32_t stBH = stAH + (uint32_t)(2 * A_SEG) * 4;
        const uint32_t stBL = stBH + (uint32_t)B_SEG * 4;

        #pragma unroll
        for (int w = 0; w < 2; w++) {
            const uint32_t wOfs = (uint32_t)(w * 8) * 4;
            uint32_t ah[2][4], al[2][4];
            ldsm_x4(ah[0][0], ah[0][1], ah[0][2], ah[0][3], stAH + lmA0 + wOfs);
            ldsm_x4(ah[1][0], ah[1][1], ah[1][2], ah[1][3], stAH + lmA1 + wOfs);
            ldsm_x4(al[0][0], al[0][1], al[0][2], al[0][3], stAL + lmA0 + wOfs);
            ldsm_x4(al[1][0], al[1][1], al[1][2], al[1][3], stAL + lmA1 + wOfs);

            #pragma unroll
            for (int ntq = 0; ntq < NTQ; ntq++) {
                const uint32_t bq = (uint32_t)(ntq * 16 * TSTR) * 4;
                uint32_t th0, th1, th2, th3, tl0, tl1, tl2, tl3;
                ldsm_x4(th0, th1, th2, th3, stBH + lmB0 + bq + wOfs);
                ldsm_x4(tl0, tl1, tl2, tl3, stBL + lmB0 + bq + wOfs);
                uint32_t bhE[2] = {th0, th2};   // nt even
                uint32_t blE[2] = {tl0, tl2};
                uint32_t bhO[2] = {th1, th3};   // nt odd
                uint32_t blO[2] = {tl1, tl3};
                #pragma unroll
                for (int mt = 0; mt < 2; mt++) {
                    mma_bf16(acc[mt][2 * ntq], al[mt], bhE);
                    mma_bf16(acc[mt][2 * ntq], ah[mt], blE);
                    mma_bf16(acc[mt][2 * ntq], ah[mt], bhE);
                    mma_bf16(acc[mt][2 * ntq + 1], al[mt], bhO);
                    mma_bf16(acc[mt][2 * ntq + 1], ah[mt], blO);
                    mma_bf16(acc[mt][2 * ntq + 1], ah[mt], bhO);
                }
            }
        }
        __syncthreads();
    }

    #pragma unroll
    for (int nt = 0; nt < NT; nt++) {
        int cbase = n0 + warpN * (NT * 8) + nt * 8 + tig * 2;
        float b0 = biasp ? __ldg(&biasp[cbase])     : 0.f;
        float b1 = biasp ? __ldg(&biasp[cbase + 1]) : 0.f;
        #pragma unroll
        for (int mt = 0; mt < 2; mt++) {
            int r0 = m0 + warpM * 32 + mt * 16 + gid;
            int r1 = r0 + 8;
            float2 o0, o1;
            o0.x = acc[mt][nt][0] + b0; o0.y = acc[mt][nt][1] + b1;
            o1.x = acc[mt][nt][2] + b0; o1.y = acc[mt][nt][3] + b1;
            if (MODE == 0) {
                float* dst = (cbase < 512) ? D0 : D1;
                int cc = cbase & 511;
                if (r0 < M) *(float2*)(dst + (size_t)r0 * 512 + cc) = o0;
                if (r1 < M) *(float2*)(dst + (size_t)r1 * 512 + cc) = o1;
            } else {
                if (r0 < M) *(float2*)(D + (size_t)r0 * 128 + cbase) = o0;
                if (r1 < M) *(float2*)(D + (size_t)r1 * 128 + cbase) = o1;
            }
        }
    }
}

// GEMM1: split UV, NT=4, occ 3
__global__ __launch_bounds__(256, 3)
void gemm1_kernel(const uint32_t* AH, const uint32_t* AL,
                  const uint32_t* Wph, const uint32_t* Wpl,
                  float* U, float* V, int M) {
    gemm_body<4, 0>(AH, AL, Wph, Wpl, PKA, nullptr, U, V, M, 0, 0);
}

// GEMM2: dual, NT=8, occ 2
__global__ __launch_bounds__(256, 2)
void gemm2_kernel(const uint32_t* AH, const uint32_t* AL,
                  const uint32_t* Wph, const uint32_t* Wpl,
                  const float* bias, float* Y2, float* P2, int M) {
    gemm_body<8, 1>(AH, AL, Wph, Wpl, PKW2, bias, Y2, P2, M, 256, 0);
}

#define NT4_SMEM_BYTES (2 * (2 * A_SEG + 2 * 64 * TSTR) * 4)    // 61440
#define NT8_SMEM_BYTES (2 * (2 * A_SEG + 2 * 128 * TSTR) * 4)   // 81920

// ---------------------------------------------------------------------------
// Launch.  Inputs: h, W1, b1, W2, b2, src, dst
// h1 = relu(h@W1_top + agg(h@W1_bot) + b1)
// out = h1@W2_top + b2 + agg(h1@W2_bot)
// ---------------------------------------------------------------------------
extern "C" void kernel_launch(void* const* d_in, const int* in_sizes, int n_in,
                              void* d_out, int out_size) {
    const float* h   = (const float*)d_in[0];
    const float* W1  = (const float*)d_in[1];
    const float* b1  = (const float*)d_in[2];
    const float* W2  = (const float*)d_in[3];
    const float* b2  = (const float*)d_in[4];
    const int*   src = (const int*)d_in[5];
    const int*   dst = (const int*)d_in[6];
    float*       out = (float*)d_out;

    float *U, *V, *Y2, *P2;
    uint32_t *hPh, *hPl, *h1Ph, *h1Pl, *W1ph, *W1pl, *W2ph, *W2pl;
    cudaGetSymbolAddress((void**)&U,    g_U);
    cudaGetSymbolAddress((void**)&V,    g_V);
    cudaGetSymbolAddress((void**)&Y2,   g_Y2);
    cudaGetSymbolAddress((void**)&P2,   g_P2);
    cudaGetSymbolAddress((void**)&hPh,  g_hPh);
    cudaGetSymbolAddress((void**)&hPl,  g_hPl);
    cudaGetSymbolAddress((void**)&h1Ph, g_h1Ph);
    cudaGetSymbolAddress((void**)&h1Pl, g_h1Pl);
    cudaGetSymbolAddress((void**)&W1ph, g_W1ph);
    cudaGetSymbolAddress((void**)&W1pl, g_W1pl);
    cudaGetSymbolAddress((void**)&W2ph, g_W2ph);
    cudaGetSymbolAddress((void**)&W2pl, g_W2pl);

    cudaFuncSetAttribute(gemm1_kernel,
                         cudaFuncAttributeMaxDynamicSharedMemorySize, NT4_SMEM_BYTES);
    cudaFuncSetAttribute(gemm2_kernel,
                         cudaFuncAttributeMaxDynamicSharedMemorySize, NT8_SMEM_BYTES);

    const int TB = 256;
    const int MT = (N_NODES + 127) / 128;  // 79

    // 1: pack W1 (fused-B layout), W2, h
    pack_all_kernel<<<dim3(76, 16), dim3(32, 8)>>>(W1, W2, h);

    // 2-3: CSR count + scan
    count_kernel<<<(N_EDGES + TB - 1) / TB, TB>>>(dst);
    scan_kernel<<<1, 1024>>>();

    // 4: GEMM1 -> U | V   (profiled launch)
    {
        dim3 grid(1024 / 64, MT);   // 16 x 79
        gemm1_kernel<<<grid, 256, NT4_SMEM_BYTES>>>(hPh, hPl, W1ph, W1pl, U, V, N_NODES);
    }

    // 5: CSR fill
    fill_kernel<<<(N_EDGES + TB - 1) / TB, TB>>>(src, dst);

    // 6: h1 = relu(U + agg(V) + b1), packed
    agg_relu_pack_kernel<<<N_NODES, 128>>>(b1);

    // 7: dual GEMM2: Y2 = h1@W2_bot, P2 = h1@W2_top + b2
    {
        dim3 grid(2, MT);
        gemm2_kernel<<<grid, 256, NT8_SMEM_BYTES>>>(h1Ph, h1Pl, W2ph, W2pl, b2, Y2, P2, N_NODES);
    }

    // 8: out = P2 + agg(Y2); re-zero cnt/cur
    agg128_final_kernel<<<(N_NODES + 3) / 4, 128>>>(out);
}

// round 16
// speedup vs baseline: 1.0502x; 1.0502x over previous
#include <cuda_runtime.h>
#include <cuda_bf16.h>
#include <stdint.h>

#define N_NODES   10000
#define N_EDGES   160000
#define F_IN      512
#define H_FEATS   512
#define N_CLASSES 128
#define PKA       (F_IN / 2)     // 256 pairs per activation row
#define PKW2      512            // pairs per W2 row (K=1024)

// ---------------------------------------------------------------------------
// Device scratch (BSS zero-init; g_cnt/g_cur re-zeroed by tail kernel)
// ---------------------------------------------------------------------------
__device__ int   g_cnt[N_NODES];
__device__ int   g_cur[N_NODES];
__device__ int   g_off[N_NODES + 1];
__device__ int   g_adj[N_EDGES];
__device__ float g_U  [(size_t)N_NODES * H_FEATS];   // h @ W1_top
__device__ float g_V  [(size_t)N_NODES * H_FEATS];   // h @ W1_bot
__device__ float g_Y2 [(size_t)N_NODES * N_CLASSES];
__device__ float g_P2 [(size_t)N_NODES * N_CLASSES];
__device__ uint32_t g_hPh [(size_t)N_NODES * PKA];
__device__ uint32_t g_hPl [(size_t)N_NODES * PKA];
__device__ uint32_t g_h1Ph[(size_t)N_NODES * PKA];
__device__ uint32_t g_h1Pl[(size_t)N_NODES * PKA];
__device__ uint32_t g_W1ph[(size_t)1024 * PKA];
__device__ uint32_t g_W1pl[(size_t)1024 * PKA];
__device__ uint32_t g_W2ph[(size_t)N_CLASSES * PKW2];
__device__ uint32_t g_W2pl[(size_t)N_CLASSES * PKW2];

// ---------------------------------------------------------------------------
// helpers
// ---------------------------------------------------------------------------
__device__ __forceinline__ void cp_async16(uint32_t dst, const void* src, int src_bytes) {
    asm volatile("cp.async.cg.shared.global [%0], [%1], 16, %2;"
                 :: "r"(dst), "l"(src), "r"(src_bytes));
}
__device__ __forceinline__ void cp_commit() {
    asm volatile("cp.async.commit_group;" ::: "memory");
}
template <int N>
__device__ __forceinline__ void cp_wait() {
    asm volatile("cp.async.wait_group %0;" :: "n"(N) : "memory");
}
__device__ __forceinline__ void mma_bf16(float* c, const uint32_t* a, const uint32_t* b) {
    asm volatile(
        "mma.sync.aligned.m16n8k16.row.col.f32.bf16.bf16.f32 "
        "{%0,%1,%2,%3}, {%4,%5,%6,%7}, {%8,%9}, {%0,%1,%2,%3};"
        : "+f"(c[0]), "+f"(c[1]), "+f"(c[2]), "+f"(c[3])
        : "r"(a[0]), "r"(a[1]), "r"(a[2]), "r"(a[3]), "r"(b[0]), "r"(b[1]));
}
__device__ __forceinline__ uint32_t pack_bf16x2(float x0, float x1) {
    uint32_t r;
    asm("cvt.rn.bf16x2.f32 %0, %1, %2;" : "=r"(r) : "f"(x1), "f"(x0));
    return r;
}
__device__ __forceinline__ void split2_bf16(float x0, float x1, uint32_t& hi, uint32_t& lo) {
    hi = pack_bf16x2(x0, x1);
    float h0 = __uint_as_float(hi << 16);
    float h1 = __uint_as_float(hi & 0xFFFF0000u);
    lo = pack_bf16x2(x0 - h0, x1 - h1);
}

// ---------------------------------------------------------------------------
// CSR build
// ---------------------------------------------------------------------------
__global__ void count_kernel(const int* __restrict__ dst) {
    int e = blockIdx.x * blockDim.x + threadIdx.x;
    if (e < N_EDGES) atomicAdd(&g_cnt[dst[e]], 1);
}
__global__ void scan_kernel() {
    __shared__ int wsum[32];
    __shared__ int chunk_total;
    const int lane = threadIdx.x & 31;
    const int wid  = threadIdx.x >> 5;
    int running = 0;
    for (int base = 0; base < N_NODES; base += 1024) {
        int i = base + threadIdx.x;
        int v = (i < N_NODES) ? g_cnt[i] : 0;
        int s = v;
        #pragma unroll
        for (int o = 1; o < 32; o <<= 1) {
            int u = __shfl_up_sync(0xffffffffu, s, o);
            if (lane >= o) s += u;
        }
        if (lane == 31) wsum[wid] = s;
        __syncthreads();
        if (wid == 0) {
            int ws = wsum[lane];
            #pragma unroll
            for (int o = 1; o < 32; o <<= 1) {
                int u = __shfl_up_sync(0xffffffffu, ws, o);
                if (lane >= o) ws += u;
            }
            wsum[lane] = ws;
            if (lane == 31) chunk_total = ws;
        }
        __syncthreads();
        int wpref = (wid > 0) ? wsum[wid - 1] : 0;
        if (i < N_NODES) g_off[i] = running + wpref + s - v;
        running += chunk_total;
        __syncthreads();
    }
    if (threadIdx.x == 0) g_off[N_NODES] = running;
}
__global__ void fill_kernel(const int* __restrict__ src, const int* __restrict__ dst) {
    int e = blockIdx.x * blockDim.x + threadIdx.x;
    if (e < N_EDGES) {
        int d = dst[e];
        int p = atomicAdd(&g_cur[d], 1);
        g_adj[g_off[d] + p] = src[e];
    }
}

// ---------------------------------------------------------------------------
// pack_all: W1 (fused-B layout), W2, and h, one launch.
// ---------------------------------------------------------------------------
__global__ void pack_all_kernel(const float* __restrict__ W1,
                                const float* __restrict__ W2,
                                const float* __restrict__ h) {
    __shared__ float sh[64][33];
    const int tx = threadIdx.x, ty = threadIdx.y;
    const int tid = ty * 32 + tx;

    if (blockIdx.x >= 36) {
        int chunk = (blockIdx.x - 36) * 16 + blockIdx.y;
        int base = chunk * 4000;
        const float2* h2 = (const float2*)h;
        for (int i = tid; i < 4000; i += 256) {
            int p = base + i;
            float2 v = h2[p];
            uint32_t hi, lo;
            split2_bf16(v.x, v.y, hi, lo);
            g_hPh[p] = hi;
            g_hPl[p] = lo;
        }
        return;
    }

    const bool isW1 = (blockIdx.x < 32);
    if (isW1 && blockIdx.y >= 8) return;

    const float* W;
    uint32_t *Wph, *Wpl;
    int srcRow0, srcCol0, srcLd, n0, ldP;
    int k0 = blockIdx.y * 64;
    if (isW1) {
        n0 = blockIdx.x * 32;
        srcRow0 = k0 + (n0 >= 512 ? 512 : 0);
        srcCol0 = n0 & 511;
        srcLd = 512;
        W = W1; Wph = g_W1ph; Wpl = g_W1pl; ldP = PKA;
    } else {
        n0 = (blockIdx.x - 32) * 32;
        srcRow0 = k0;
        srcCol0 = n0;
        srcLd = 128;
        W = W2; Wph = g_W2ph; Wpl = g_W2pl; ldP = PKW2;
    }

    #pragma unroll
    for (int j = 0; j < 64; j += 8)
        sh[j + ty][tx] = W[(size_t)(srcRow0 + j + ty) * srcLd + srcCol0 + tx];
    __syncthreads();
    #pragma unroll
    for (int j = 0; j < 32; j += 8) {
        int nl = ty + j;
        float x0 = sh[2 * tx][nl];
        float x1 = sh[2 * tx + 1][nl];
        uint32_t hi, lo;
        split2_bf16(x0, x1, hi, lo);
        size_t o = (size_t)(n0 + nl) * ldP + (k0 >> 1) + tx;
        Wph[o] = hi;
        Wpl[o] = lo;
    }
}

// ---------------------------------------------------------------------------
// Fused layer-1 tail: h1 = relu(U[n] + mean V[neigh] + b1), packed out.
// ---------------------------------------------------------------------------
__global__ void agg_relu_pack_kernel(const float* __restrict__ b1) {
    int n   = blockIdx.x;
    int st  = g_off[n];
    int deg = g_off[n + 1] - st;
    int c4  = threadIdx.x;

    float4 acc = make_float4(0.f, 0.f, 0.f, 0.f);
    int e = 0;
    for (; e + 1 < deg; e += 2) {
        int s0 = g_adj[st + e];
        int s1 = g_adj[st + e + 1];
        float4 v0 = *(const float4*)(g_V + (size_t)s0 * 512 + c4 * 4);
        float4 v1 = *(const float4*)(g_V + (size_t)s1 * 512 + c4 * 4);
        acc.x += v0.x + v1.x; acc.y += v0.y + v1.y;
        acc.z += v0.z + v1.z; acc.w += v0.w + v1.w;
    }
    if (e < deg) {
        int s0 = g_adj[st + e];
        float4 v0 = *(const float4*)(g_V + (size_t)s0 * 512 + c4 * 4);
        acc.x += v0.x; acc.y += v0.y; acc.z += v0.z; acc.w += v0.w;
    }
    float inv = (deg > 0) ? (1.0f / (float)deg) : 0.0f;
    float4 u = *(const float4*)(g_U + (size_t)n * 512 + c4 * 4);
    float4 b = *(const float4*)(b1 + c4 * 4);
    float v0 = fmaxf(u.x + acc.x * inv + b.x, 0.f);
    float v1 = fmaxf(u.y + acc.y * inv + b.y, 0.f);
    float v2 = fmaxf(u.z + acc.z * inv + b.z, 0.f);
    float v3 = fmaxf(u.w + acc.w * inv + b.w, 0.f);
    uint32_t h0, l0, h1, l1;
    split2_bf16(v0, v1, h0, l0);
    split2_bf16(v2, v3, h1, l1);
    ((uint2*)(g_h1Ph + (size_t)n * PKA))[c4] = make_uint2(h0, h1);
    ((uint2*)(g_h1Pl + (size_t)n * PKA))[c4] = make_uint2(l0, l1);
}

// out[n] = P2[n] + mean Y2[neigh]; re-zero cnt/cur for next call
__global__ void agg128_final_kernel(float* __restrict__ out) {
    int gi = blockIdx.x * blockDim.x + threadIdx.x;
    if (gi < N_NODES) { g_cnt[gi] = 0; g_cur[gi] = 0; }

    int n = blockIdx.x * 4 + (threadIdx.x >> 5);
    int lane = threadIdx.x & 31;
    if (n >= N_NODES) return;
    int st  = g_off[n];
    int deg = g_off[n + 1] - st;
    float4 acc = make_float4(0.f, 0.f, 0.f, 0.f);
    int e = 0;
    for (; e + 1 < deg; e += 2) {
        int s0 = g_adj[st + e];
        int s1 = g_adj[st + e + 1];
        float4 v0 = *(const float4*)(g_Y2 + (size_t)s0 * 128 + lane * 4);
        float4 v1 = *(const float4*)(g_Y2 + (size_t)s1 * 128 + lane * 4);
        acc.x += v0.x + v1.x; acc.y += v0.y + v1.y;
        acc.z += v0.z + v1.z; acc.w += v0.w + v1.w;
    }
    if (e < deg) {
        int s0 = g_adj[st + e];
        float4 v0 = *(const float4*)(g_Y2 + (size_t)s0 * 128 + lane * 4);
        acc.x += v0.x; acc.y += v0.y; acc.z += v0.z; acc.w += v0.w;
    }
    float inv = (deg > 0) ? (1.0f / (float)deg) : 0.0f;
    float4 p = *(const float4*)(g_P2 + (size_t)n * 128 + lane * 4);
    acc.x = acc.x * inv + p.x; acc.y = acc.y * inv + p.y;
    acc.z = acc.z * inv + p.z; acc.w = acc.w * inv + p.w;
    *(float4*)(out + (size_t)n * 128 + lane * 4) = acc;
}

// ---------------------------------------------------------------------------
// bf16x3 GEMM (scalar-LDS fragments, round-14 proven inner loop).
// K=512 (16 stages of BK=32). MODE 0: split-UV output (U cols<512, V else).
// MODE 1: dual output (bx=0 -> Y2 @koffp0; bx=1 -> P2+bias @koffp1).
// Both use NT=8 (block 128x128, warp tile 32x64), occ 2.
// ---------------------------------------------------------------------------
#define TSTR 20
#define A_SEG (128 * TSTR)
#define NSTAGES 16

template <int NT, int MODE>
__device__ __forceinline__ void gemm_body(
        const uint32_t* __restrict__ AH, const uint32_t* __restrict__ AL,
        const uint32_t* __restrict__ Wph, const uint32_t* __restrict__ Wpl, int ldP,
        const float* __restrict__ bias,
        float* __restrict__ D0, float* __restrict__ D1,
        int M, int koffp0, int koffp1) {
    extern __shared__ uint32_t smem[];

    constexpr int BN    = 16 * NT;
    constexpr int B_SEG = BN * TSTR;
    constexpr int STAGE_W = 2 * A_SEG + 2 * B_SEG;

    const int t     = threadIdx.x;
    const int lane  = t & 31;
    const int wid   = t >> 5;
    const int warpM = wid & 3;
    const int warpN = wid >> 2;
    const int gid   = lane >> 2;
    const int tig   = lane & 3;
    const int m0    = blockIdx.y * 128;

    int n0, koffp;
    float* D = D0;
    const float* biasp = nullptr;
    if (MODE == 0) {
        n0 = blockIdx.x * BN;
        koffp = koffp0;
    } else {
        n0 = 0;
        if (blockIdx.x == 0) { D = D0; koffp = koffp0; }
        else                 { D = D1; koffp = koffp1; biasp = bias; }
    }

    const int lrow  = t >> 1;
    const int lhw   = (t & 1) * 8;
    const int aRow  = m0 + lrow;
    const int aOK   = (aRow < M) ? 16 : 0;
    const int aRowC = (aRow < M) ? aRow : 0;
    const int bRow = (NT == 8) ? (t >> 1) : (t >> 2);
    const int bW   = (NT == 8) ? ((t & 1) * 8) : ((t & 3) * 4);
    const uint32_t* WphRow = Wph + (size_t)(n0 + bRow) * ldP + koffp;
    const uint32_t* WplRow = Wpl + (size_t)(n0 + bRow) * ldP + koffp;

    float acc[2][NT][4];
    #pragma unroll
    for (int mt = 0; mt < 2; mt++)
        #pragma unroll
        for (int nt = 0; nt < NT; nt++)
            #pragma unroll
            for (int q = 0; q < 4; q++) acc[mt][nt][q] = 0.f;

    const uint32_t smemBase = (uint32_t)__cvta_generic_to_shared(smem);
    const uint32_t aOfs = (uint32_t)(lrow * TSTR + lhw) * 4;
    const uint32_t bOfs = (uint32_t)(bRow * TSTR + bW) * 4;

    auto load_stage = [&](int s, int bf) {
        uint32_t stB = smemBase + (uint32_t)(bf * STAGE_W) * 4;
        const int pb = s * 16;
        const uint32_t* ah = AH + (size_t)aRowC * PKA + pb + lhw;
        const uint32_t* al = AL + (size_t)aRowC * PKA + pb + lhw;
        cp_async16(stB + aOfs,                  ah,     aOK);
        cp_async16(stB + aOfs + 16,             ah + 4, aOK);
        cp_async16(stB + A_SEG * 4 + aOfs,      al,     aOK);
        cp_async16(stB + A_SEG * 4 + aOfs + 16, al + 4, aOK);
        uint32_t bhB = stB + 2 * A_SEG * 4 + bOfs;
        uint32_t blB = bhB + B_SEG * 4;
        const uint32_t* bh = WphRow + pb + bW;
        const uint32_t* bl = WplRow + pb + bW;
        if (NT == 8) {
            cp_async16(bhB,      bh,     16);
            cp_async16(bhB + 16, bh + 4, 16);
            cp_async16(blB,      bl,     16);
            cp_async16(blB + 16, bl + 4, 16);
        } else {
            cp_async16(bhB, bh, 16);
            cp_async16(blB, bl, 16);
        }
    };

    load_stage(0, 0);
    cp_commit();

    for (int s = 0; s < NSTAGES; s++) {
        const int bf = s & 1;
        if (s + 1 < NSTAGES) { load_stage(s + 1, bf ^ 1); cp_commit(); cp_wait<1>(); }
        else                 { cp_wait<0>(); }
        __syncthreads();

        const uint32_t* AHb = smem + bf * STAGE_W;
        const uint32_t* ALb = AHb + A_SEG;
        const uint32_t* BHb = AHb + 2 * A_SEG;
        const uint32_t* BLb = BHb + B_SEG;

        #pragma unroll
        for (int w = 0; w < 2; w++) {
            uint32_t ah[2][4], al[2][4];
            #pragma unroll
            for (int mt = 0; mt < 2; mt++) {
                int r = warpM * 32 + mt * 16 + gid;
                int b0 = r * TSTR + w * 8 + tig;
                ah[mt][0] = AHb[b0];
                ah[mt][1] = AHb[b0 + 8 * TSTR];
                ah[mt][2] = AHb[b0 + 4];
                ah[mt][3] = AHb[b0 + 8 * TSTR + 4];
                al[mt][0] = ALb[b0];
                al[mt][1] = ALb[b0 + 8 * TSTR];
                al[mt][2] = ALb[b0 + 4];
                al[mt][3] = ALb[b0 + 8 * TSTR + 4];
            }
            #pragma unroll
            for (int nt = 0; nt < NT; nt++) {
                int n = warpN * (NT * 8) + nt * 8 + gid;
                int nb = n * TSTR + w * 8 + tig;
                uint32_t bh[2], bl[2];
                bh[0] = BHb[nb];
                bh[1] = BHb[nb + 4];
                bl[0] = BLb[nb];
                bl[1] = BLb[nb + 4];
                #pragma unroll
                for (int mt = 0; mt < 2; mt++) {
                    mma_bf16(acc[mt][nt], al[mt], bh);
                    mma_bf16(acc[mt][nt], ah[mt], bl);
                    mma_bf16(acc[mt][nt], ah[mt], bh);
                }
            }
        }
        __syncthreads();
    }

    #pragma unroll
    for (int nt = 0; nt < NT; nt++) {
        int cbase = n0 + warpN * (NT * 8) + nt * 8 + tig * 2;
        float b0 = biasp ? __ldg(&biasp[cbase])     : 0.f;
        float b1 = biasp ? __ldg(&biasp[cbase + 1]) : 0.f;
        #pragma unroll
        for (int mt = 0; mt < 2; mt++) {
            int r0 = m0 + warpM * 32 + mt * 16 + gid;
            int r1 = r0 + 8;
            float2 o0, o1;
            o0.x = acc[mt][nt][0] + b0; o0.y = acc[mt][nt][1] + b1;
            o1.x = acc[mt][nt][2] + b0; o1.y = acc[mt][nt][3] + b1;
            if (MODE == 0) {
                float* dst = (cbase < 512) ? D0 : D1;
                int cc = cbase & 511;
                if (r0 < M) *(float2*)(dst + (size_t)r0 * 512 + cc) = o0;
                if (r1 < M) *(float2*)(dst + (size_t)r1 * 512 + cc) = o1;
            } else {
                if (r0 < M) *(float2*)(D + (size_t)r0 * 128 + cbase) = o0;
                if (r1 < M) *(float2*)(D + (size_t)r1 * 128 + cbase) = o1;
            }
        }
    }
}

// GEMM1: split UV, NT=8 (128x128 tile), occ 2
__global__ __launch_bounds__(256, 2)
void gemm1_kernel(const uint32_t* AH, const uint32_t* AL,
                  const uint32_t* Wph, const uint32_t* Wpl,
                  float* U, float* V, int M) {
    gemm_body<8, 0>(AH, AL, Wph, Wpl, PKA, nullptr, U, V, M, 0, 0);
}

// GEMM2: dual, NT=8, occ 2
__global__ __launch_bounds__(256, 2)
void gemm2_kernel(const uint32_t* AH, const uint32_t* AL,
                  const uint32_t* Wph, const uint32_t* Wpl,
                  const float* bias, float* Y2, float* P2, int M) {
    gemm_body<8, 1>(AH, AL, Wph, Wpl, PKW2, bias, Y2, P2, M, 256, 0);
}

#define NT8_SMEM_BYTES (2 * (2 * A_SEG + 2 * 128 * TSTR) * 4)   // 81920

// ---------------------------------------------------------------------------
// Launch.  Inputs: h, W1, b1, W2, b2, src, dst
// h1 = relu(h@W1_top + agg(h@W1_bot) + b1)
// out = h1@W2_top + b2 + agg(h1@W2_bot)
// ---------------------------------------------------------------------------
extern "C" void kernel_launch(void* const* d_in, const int* in_sizes, int n_in,
                              void* d_out, int out_size) {
    const float* h   = (const float*)d_in[0];
    const float* W1  = (const float*)d_in[1];
    const float* b1  = (const float*)d_in[2];
    const float* W2  = (const float*)d_in[3];
    const float* b2  = (const float*)d_in[4];
    const int*   src = (const int*)d_in[5];
    const int*   dst = (const int*)d_in[6];
    float*       out = (float*)d_out;

    float *U, *V, *Y2, *P2;
    uint32_t *hPh, *hPl, *h1Ph, *h1Pl, *W1ph, *W1pl, *W2ph, *W2pl;
    cudaGetSymbolAddress((void**)&U,    g_U);
    cudaGetSymbolAddress((void**)&V,    g_V);
    cudaGetSymbolAddress((void**)&Y2,   g_Y2);
    cudaGetSymbolAddress((void**)&P2,   g_P2);
    cudaGetSymbolAddress((void**)&hPh,  g_hPh);
    cudaGetSymbolAddress((void**)&hPl,  g_hPl);
    cudaGetSymbolAddress((void**)&h1Ph, g_h1Ph);
    cudaGetSymbolAddress((void**)&h1Pl, g_h1Pl);
    cudaGetSymbolAddress((void**)&W1ph, g_W1ph);
    cudaGetSymbolAddress((void**)&W1pl, g_W1pl);
    cudaGetSymbolAddress((void**)&W2ph, g_W2ph);
    cudaGetSymbolAddress((void**)&W2pl, g_W2pl);

    cudaFuncSetAttribute(gemm1_kernel,
                         cudaFuncAttributeMaxDynamicSharedMemorySize, NT8_SMEM_BYTES);
    cudaFuncSetAttribute(gemm2_kernel,
                         cudaFuncAttributeMaxDynamicSharedMemorySize, NT8_SMEM_BYTES);

    const int TB = 256;
    const int MT = (N_NODES + 127) / 128;  // 79

    // 1: pack W1 (fused-B layout), W2, h
    pack_all_kernel<<<dim3(76, 16), dim3(32, 8)>>>(W1, W2, h);

    // 2-3: CSR count + scan
    count_kernel<<<(N_EDGES + TB - 1) / TB, TB>>>(dst);
    scan_kernel<<<1, 1024>>>();

    // 4: GEMM1 -> U | V   (profiled launch), 128x128 tiles, 632 CTAs
    {
        dim3 grid(1024 / 128, MT);   // 8 x 79
        gemm1_kernel<<<grid, 256, NT8_SMEM_BYTES>>>(hPh, hPl, W1ph, W1pl, U, V, N_NODES);
    }

    // 5: CSR fill
    fill_kernel<<<(N_EDGES + TB - 1) / TB, TB>>>(src, dst);

    // 6: h1 = relu(U + agg(V) + b1), packed
    agg_relu_pack_kernel<<<N_NODES, 128>>>(b1);

    // 7: dual GEMM2: Y2 = h1@W2_bot, P2 = h1@W2_top + b2
    {
        dim3 grid(2, MT);
        gemm2_kernel<<<grid, 256, NT8_SMEM_BYTES>>>(h1Ph, h1Pl, W2ph, W2pl, b2, Y2, P2, N_NODES);
    }

    // 8: out = P2 + agg(Y2); re-zero cnt/cur
    agg128_final_kernel<<<(N_NODES + 3) / 4, 128>>>(out);
}

// round 17
// speedup vs baseline: 1.0562x; 1.0057x over previous
#include <cuda_runtime.h>
#include <cuda_bf16.h>
#include <stdint.h>

#define N_NODES   10000
#define N_EDGES   160000
#define F_IN      512
#define H_FEATS   512
#define N_CLASSES 128
#define PKA       (F_IN / 2)     // 256 pairs per activation row
#define PKW2      512            // pairs per W2 row (K=1024)

// ---------------------------------------------------------------------------
// Device scratch (BSS zero-init; g_cnt/g_cur re-zeroed by tail kernel)
// ---------------------------------------------------------------------------
__device__ int   g_cnt[N_NODES];
__device__ int   g_cur[N_NODES];
__device__ int   g_off[N_NODES + 1];
__device__ int   g_adj[N_EDGES];
__device__ float g_U  [(size_t)N_NODES * H_FEATS];   // h @ W1_top
__device__ float g_V  [(size_t)N_NODES * H_FEATS];   // h @ W1_bot
__device__ float g_Y2 [(size_t)N_NODES * N_CLASSES];
__device__ float g_P2 [(size_t)N_NODES * N_CLASSES];
__device__ uint32_t g_hPh [(size_t)N_NODES * PKA];
__device__ uint32_t g_hPl [(size_t)N_NODES * PKA];
__device__ uint32_t g_h1Ph[(size_t)N_NODES * PKA];
__device__ uint32_t g_h1Pl[(size_t)N_NODES * PKA];
__device__ uint32_t g_W1ph[(size_t)1024 * PKA];
__device__ uint32_t g_W1pl[(size_t)1024 * PKA];
__device__ uint32_t g_W2ph[(size_t)N_CLASSES * PKW2];
__device__ uint32_t g_W2pl[(size_t)N_CLASSES * PKW2];

// ---------------------------------------------------------------------------
// helpers
// ---------------------------------------------------------------------------
__device__ __forceinline__ void cp_async16(uint32_t dst, const void* src, int src_bytes) {
    asm volatile("cp.async.cg.shared.global [%0], [%1], 16, %2;"
                 :: "r"(dst), "l"(src), "r"(src_bytes));
}
__device__ __forceinline__ void cp_commit() {
    asm volatile("cp.async.commit_group;" ::: "memory");
}
template <int N>
__device__ __forceinline__ void cp_wait() {
    asm volatile("cp.async.wait_group %0;" :: "n"(N) : "memory");
}
__device__ __forceinline__ void mma_bf16(float* c, const uint32_t* a, const uint32_t* b) {
    asm volatile(
        "mma.sync.aligned.m16n8k16.row.col.f32.bf16.bf16.f32 "
        "{%0,%1,%2,%3}, {%4,%5,%6,%7}, {%8,%9}, {%0,%1,%2,%3};"
        : "+f"(c[0]), "+f"(c[1]), "+f"(c[2]), "+f"(c[3])
        : "r"(a[0]), "r"(a[1]), "r"(a[2]), "r"(a[3]), "r"(b[0]), "r"(b[1]));
}
__device__ __forceinline__ uint32_t pack_bf16x2(float x0, float x1) {
    uint32_t r;
    asm("cvt.rn.bf16x2.f32 %0, %1, %2;" : "=r"(r) : "f"(x1), "f"(x0));
    return r;
}
__device__ __forceinline__ void split2_bf16(float x0, float x1, uint32_t& hi, uint32_t& lo) {
    hi = pack_bf16x2(x0, x1);
    float h0 = __uint_as_float(hi << 16);
    float h1 = __uint_as_float(hi & 0xFFFF0000u);
    lo = pack_bf16x2(x0 - h0, x1 - h1);
}

// ---------------------------------------------------------------------------
// scan (single block)
// ---------------------------------------------------------------------------
__global__ void scan_kernel() {
    __shared__ int wsum[32];
    __shared__ int chunk_total;
    const int lane = threadIdx.x & 31;
    const int wid  = threadIdx.x >> 5;
    int running = 0;
    for (int base = 0; base < N_NODES; base += 1024) {
        int i = base + threadIdx.x;
        int v = (i < N_NODES) ? g_cnt[i] : 0;
        int s = v;
        #pragma unroll
        for (int o = 1; o < 32; o <<= 1) {
            int u = __shfl_up_sync(0xffffffffu, s, o);
            if (lane >= o) s += u;
        }
        if (lane == 31) wsum[wid] = s;
        __syncthreads();
        if (wid == 0) {
            int ws = wsum[lane];
            #pragma unroll
            for (int o = 1; o < 32; o <<= 1) {
                int u = __shfl_up_sync(0xffffffffu, ws, o);
                if (lane >= o) ws += u;
            }
            wsum[lane] = ws;
            if (lane == 31) chunk_total = ws;
        }
        __syncthreads();
        int wpref = (wid > 0) ? wsum[wid - 1] : 0;
        if (i < N_NODES) g_off[i] = running + wpref + s - v;
        running += chunk_total;
        __syncthreads();
    }
    if (threadIdx.x == 0) g_off[N_NODES] = running;
}

// ---------------------------------------------------------------------------
// pack_all + count fused: W1 (fused-B layout), W2, h, and degree count.
// grid (77, 16), block (32, 8):
//   bx <  32 : W1 pack   (by < 8 only)
//   32<=bx<36: W2 pack
//   36<=bx<76: h pack    chunk = (bx-36)*16 + by
//   bx == 76 : count     (16 blocks x 256 thr, stride loop over edges)
// ---------------------------------------------------------------------------
__global__ void pack_all_kernel(const float* __restrict__ W1,
                                const float* __restrict__ W2,
                                const float* __restrict__ h,
                                const int* __restrict__ dst) {
    __shared__ float sh[64][33];
    const int tx = threadIdx.x, ty = threadIdx.y;
    const int tid = ty * 32 + tx;

    if (blockIdx.x == 76) {
        int g = blockIdx.y * 256 + tid;
        for (int e = g; e < N_EDGES; e += 16 * 256)
            atomicAdd(&g_cnt[dst[e]], 1);
        return;
    }

    if (blockIdx.x >= 36) {
        int chunk = (blockIdx.x - 36) * 16 + blockIdx.y;
        int base = chunk * 4000;
        const float2* h2 = (const float2*)h;
        for (int i = tid; i < 4000; i += 256) {
            int p = base + i;
            float2 v = h2[p];
            uint32_t hi, lo;
            split2_bf16(v.x, v.y, hi, lo);
            g_hPh[p] = hi;
            g_hPl[p] = lo;
        }
        return;
    }

    const bool isW1 = (blockIdx.x < 32);
    if (isW1 && blockIdx.y >= 8) return;

    const float* W;
    uint32_t *Wph, *Wpl;
    int srcRow0, srcCol0, srcLd, n0, ldP;
    int k0 = blockIdx.y * 64;
    if (isW1) {
        n0 = blockIdx.x * 32;
        srcRow0 = k0 + (n0 >= 512 ? 512 : 0);
        srcCol0 = n0 & 511;
        srcLd = 512;
        W = W1; Wph = g_W1ph; Wpl = g_W1pl; ldP = PKA;
    } else {
        n0 = (blockIdx.x - 32) * 32;
        srcRow0 = k0;
        srcCol0 = n0;
        srcLd = 128;
        W = W2; Wph = g_W2ph; Wpl = g_W2pl; ldP = PKW2;
    }

    #pragma unroll
    for (int j = 0; j < 64; j += 8)
        sh[j + ty][tx] = W[(size_t)(srcRow0 + j + ty) * srcLd + srcCol0 + tx];
    __syncthreads();
    #pragma unroll
    for (int j = 0; j < 32; j += 8) {
        int nl = ty + j;
        float x0 = sh[2 * tx][nl];
        float x1 = sh[2 * tx + 1][nl];
        uint32_t hi, lo;
        split2_bf16(x0, x1, hi, lo);
        size_t o = (size_t)(n0 + nl) * ldP + (k0 >> 1) + tx;
        Wph[o] = hi;
        Wpl[o] = lo;
    }
}

// ---------------------------------------------------------------------------
// Fused layer-1 tail: h1 = relu(U[n] + mean V[neigh] + b1), packed out.
// ---------------------------------------------------------------------------
__global__ void agg_relu_pack_kernel(const float* __restrict__ b1) {
    int n   = blockIdx.x;
    int st  = g_off[n];
    int deg = g_off[n + 1] - st;
    int c4  = threadIdx.x;

    float4 acc = make_float4(0.f, 0.f, 0.f, 0.f);
    int e = 0;
    for (; e + 1 < deg; e += 2) {
        int s0 = g_adj[st + e];
        int s1 = g_adj[st + e + 1];
        float4 v0 = *(const float4*)(g_V + (size_t)s0 * 512 + c4 * 4);
        float4 v1 = *(const float4*)(g_V + (size_t)s1 * 512 + c4 * 4);
        acc.x += v0.x + v1.x; acc.y += v0.y + v1.y;
        acc.z += v0.z + v1.z; acc.w += v0.w + v1.w;
    }
    if (e < deg) {
        int s0 = g_adj[st + e];
        float4 v0 = *(const float4*)(g_V + (size_t)s0 * 512 + c4 * 4);
        acc.x += v0.x; acc.y += v0.y; acc.z += v0.z; acc.w += v0.w;
    }
    float inv = (deg > 0) ? (1.0f / (float)deg) : 0.0f;
    float4 u = *(const float4*)(g_U + (size_t)n * 512 + c4 * 4);
    float4 b = *(const float4*)(b1 + c4 * 4);
    float v0 = fmaxf(u.x + acc.x * inv + b.x, 0.f);
    float v1 = fmaxf(u.y + acc.y * inv + b.y, 0.f);
    float v2 = fmaxf(u.z + acc.z * inv + b.z, 0.f);
    float v3 = fmaxf(u.w + acc.w * inv + b.w, 0.f);
    uint32_t h0, l0, h1, l1;
    split2_bf16(v0, v1, h0, l0);
    split2_bf16(v2, v3, h1, l1);
    ((uint2*)(g_h1Ph + (size_t)n * PKA))[c4] = make_uint2(h0, h1);
    ((uint2*)(g_h1Pl + (size_t)n * PKA))[c4] = make_uint2(l0, l1);
}

// out[n] = P2[n] + mean Y2[neigh]; re-zero cnt/cur for next call
__global__ void agg128_final_kernel(float* __restrict__ out) {
    int gi = blockIdx.x * blockDim.x + threadIdx.x;
    if (gi < N_NODES) { g_cnt[gi] = 0; g_cur[gi] = 0; }

    int n = blockIdx.x * 4 + (threadIdx.x >> 5);
    int lane = threadIdx.x & 31;
    if (n >= N_NODES) return;
    int st  = g_off[n];
    int deg = g_off[n + 1] - st;
    float4 acc = make_float4(0.f, 0.f, 0.f, 0.f);
    int e = 0;
    for (; e + 1 < deg; e += 2) {
        int s0 = g_adj[st + e];
        int s1 = g_adj[st + e + 1];
        float4 v0 = *(const float4*)(g_Y2 + (size_t)s0 * 128 + lane * 4);
        float4 v1 = *(const float4*)(g_Y2 + (size_t)s1 * 128 + lane * 4);
        acc.x += v0.x + v1.x; acc.y += v0.y + v1.y;
        acc.z += v0.z + v1.z; acc.w += v0.w + v1.w;
    }
    if (e < deg) {
        int s0 = g_adj[st + e];
        float4 v0 = *(const float4*)(g_Y2 + (size_t)s0 * 128 + lane * 4);
        acc.x += v0.x; acc.y += v0.y; acc.z += v0.z; acc.w += v0.w;
    }
    float inv = (deg > 0) ? (1.0f / (float)deg) : 0.0f;
    float4 p = *(const float4*)(g_P2 + (size_t)n * 128 + lane * 4);
    acc.x = acc.x * inv + p.x; acc.y = acc.y * inv + p.y;
    acc.z = acc.z * inv + p.z; acc.w = acc.w * inv + p.w;
    *(float4*)(out + (size_t)n * 128 + lane * 4) = acc;
}

// ---------------------------------------------------------------------------
// bf16x3 GEMM (scalar-LDS fragments).  K=512 (16 stages of BK=32), NT=8.
// MODE 0: split-UV output.  MODE 1: dual output (Y2 / P2+bias).
// ---------------------------------------------------------------------------
#define TSTR 20
#define A_SEG (128 * TSTR)
#define NSTAGES 16

template <int NT, int MODE>
__device__ __forceinline__ void gemm_body(
        const uint32_t* __restrict__ AH, const uint32_t* __restrict__ AL,
        const uint32_t* __restrict__ Wph, const uint32_t* __restrict__ Wpl, int ldP,
        const float* __restrict__ bias,
        float* __restrict__ D0, float* __restrict__ D1,
        int M, int koffp0, int koffp1) {
    extern __shared__ uint32_t smem[];

    constexpr int BN    = 16 * NT;
    constexpr int B_SEG = BN * TSTR;
    constexpr int STAGE_W = 2 * A_SEG + 2 * B_SEG;

    const int t     = threadIdx.x;
    const int lane  = t & 31;
    const int wid   = t >> 5;
    const int warpM = wid & 3;
    const int warpN = wid >> 2;
    const int gid   = lane >> 2;
    const int tig   = lane & 3;
    const int m0    = blockIdx.y * 128;

    int n0, koffp;
    float* D = D0;
    const float* biasp = nullptr;
    if (MODE == 0) {
        n0 = blockIdx.x * BN;
        koffp = koffp0;
    } else {
        n0 = 0;
        if (blockIdx.x == 0) { D = D0; koffp = koffp0; }
        else                 { D = D1; koffp = koffp1; biasp = bias; }
    }

    const int lrow  = t >> 1;
    const int lhw   = (t & 1) * 8;
    const int aRow  = m0 + lrow;
    const int aOK   = (aRow < M) ? 16 : 0;
    const int aRowC = (aRow < M) ? aRow : 0;
    const int bRow = t >> 1;
    const int bW   = (t & 1) * 8;
    const uint32_t* WphRow = Wph + (size_t)(n0 + bRow) * ldP + koffp;
    const uint32_t* WplRow = Wpl + (size_t)(n0 + bRow) * ldP + koffp;

    float acc[2][NT][4];
    #pragma unroll
    for (int mt = 0; mt < 2; mt++)
        #pragma unroll
        for (int nt = 0; nt < NT; nt++)
            #pragma unroll
            for (int q = 0; q < 4; q++) acc[mt][nt][q] = 0.f;

    const uint32_t smemBase = (uint32_t)__cvta_generic_to_shared(smem);
    const uint32_t aOfs = (uint32_t)(lrow * TSTR + lhw) * 4;
    const uint32_t bOfs = (uint32_t)(bRow * TSTR + bW) * 4;

    auto load_stage = [&](int s, int bf) {
        uint32_t stB = smemBase + (uint32_t)(bf * STAGE_W) * 4;
        const int pb = s * 16;
        const uint32_t* ah = AH + (size_t)aRowC * PKA + pb + lhw;
        const uint32_t* al = AL + (size_t)aRowC * PKA + pb + lhw;
        cp_async16(stB + aOfs,                  ah,     aOK);
        cp_async16(stB + aOfs + 16,             ah + 4, aOK);
        cp_async16(stB + A_SEG * 4 + aOfs,      al,     aOK);
        cp_async16(stB + A_SEG * 4 + aOfs + 16, al + 4, aOK);
        uint32_t bhB = stB + 2 * A_SEG * 4 + bOfs;
        uint32_t blB = bhB + B_SEG * 4;
        const uint32_t* bh = WphRow + pb + bW;
        const uint32_t* bl = WplRow + pb + bW;
        cp_async16(bhB,      bh,     16);
        cp_async16(bhB + 16, bh + 4, 16);
        cp_async16(blB,      bl,     16);
        cp_async16(blB + 16, bl + 4, 16);
    };

    load_stage(0, 0);
    cp_commit();

    for (int s = 0; s < NSTAGES; s++) {
        const int bf = s & 1;
        if (s + 1 < NSTAGES) { load_stage(s + 1, bf ^ 1); cp_commit(); cp_wait<1>(); }
        else                 { cp_wait<0>(); }
        __syncthreads();

        const uint32_t* AHb = smem + bf * STAGE_W;
        const uint32_t* ALb = AHb + A_SEG;
        const uint32_t* BHb = AHb + 2 * A_SEG;
        const uint32_t* BLb = BHb + B_SEG;

        #pragma unroll
        for (int w = 0; w < 2; w++) {
            uint32_t ah[2][4], al[2][4];
            #pragma unroll
            for (int mt = 0; mt < 2; mt++) {
                int r = warpM * 32 + mt * 16 + gid;
                int b0 = r * TSTR + w * 8 + tig;
                ah[mt][0] = AHb[b0];
                ah[mt][1] = AHb[b0 + 8 * TSTR];
                ah[mt][2] = AHb[b0 + 4];
                ah[mt][3] = AHb[b0 + 8 * TSTR + 4];
                al[mt][0] = ALb[b0];
                al[mt][1] = ALb[b0 + 8 * TSTR];
                al[mt][2] = ALb[b0 + 4];
                al[mt][3] = ALb[b0 + 8 * TSTR + 4];
            }
            #pragma unroll
            for (int nt = 0; nt < NT; nt++) {
                int n = warpN * (NT * 8) + nt * 8 + gid;
                int nb = n * TSTR + w * 8 + tig;
                uint32_t bh[2], bl[2];
                bh[0] = BHb[nb];
                bh[1] = BHb[nb + 4];
                bl[0] = BLb[nb];
                bl[1] = BLb[nb + 4];
                #pragma unroll
                for (int mt = 0; mt < 2; mt++) {
                    mma_bf16(acc[mt][nt], al[mt], bh);
                    mma_bf16(acc[mt][nt], ah[mt], bl);
                    mma_bf16(acc[mt][nt], ah[mt], bh);
                }
            }
        }
        __syncthreads();
    }

    #pragma unroll
    for (int nt = 0; nt < NT; nt++) {
        int cbase = n0 + warpN * (NT * 8) + nt * 8 + tig * 2;
        float b0 = biasp ? __ldg(&biasp[cbase])     : 0.f;
        float b1 = biasp ? __ldg(&biasp[cbase + 1]) : 0.f;
        #pragma unroll
        for (int mt = 0; mt < 2; mt++) {
            int r0 = m0 + warpM * 32 + mt * 16 + gid;
            int r1 = r0 + 8;
            float2 o0, o1;
            o0.x = acc[mt][nt][0] + b0; o0.y = acc[mt][nt][1] + b1;
            o1.x = acc[mt][nt][2] + b0; o1.y = acc[mt][nt][3] + b1;
            if (MODE == 0) {
                float* dst = (cbase < 512) ? D0 : D1;
                int cc = cbase & 511;
                if (r0 < M) *(float2*)(dst + (size_t)r0 * 512 + cc) = o0;
                if (r1 < M) *(float2*)(dst + (size_t)r1 * 512 + cc) = o1;
            } else {
                if (r0 < M) *(float2*)(D + (size_t)r0 * 128 + cbase) = o0;
                if (r1 < M) *(float2*)(D + (size_t)r1 * 128 + cbase) = o1;
            }
        }
    }
}

// GEMM1 + fused CSR fill: blockIdx.x < 8 -> GEMM tiles; == 8 -> fill role.
__global__ __launch_bounds__(256, 2)
void gemm1_kernel(const uint32_t* AH, const uint32_t* AL,
                  const uint32_t* Wph, const uint32_t* Wpl,
                  float* U, float* V, int M,
                  const int* __restrict__ src, const int* __restrict__ dst) {
    if (blockIdx.x == 8) {
        int g = blockIdx.y * 256 + threadIdx.x;
        const int stride = 79 * 256;
        for (int e = g; e < N_EDGES; e += stride) {
            int d = dst[e];
            int p = atomicAdd(&g_cur[d], 1);
            g_adj[g_off[d] + p] = src[e];
        }
        return;
    }
    gemm_body<8, 0>(AH, AL, Wph, Wpl, PKA, nullptr, U, V, M, 0, 0);
}

// GEMM2: dual, NT=8, occ 2
__global__ __launch_bounds__(256, 2)
void gemm2_kernel(const uint32_t* AH, const uint32_t* AL,
                  const uint32_t* Wph, const uint32_t* Wpl,
                  const float* bias, float* Y2, float* P2, int M) {
    gemm_body<8, 1>(AH, AL, Wph, Wpl, PKW2, bias, Y2, P2, M, 256, 0);
}

#define NT8_SMEM_BYTES (2 * (2 * A_SEG + 2 * 128 * TSTR) * 4)   // 81920

// ---------------------------------------------------------------------------
// Launch.  Inputs: h, W1, b1, W2, b2, src, dst
// h1 = relu(h@W1_top + agg(h@W1_bot) + b1)
// out = h1@W2_top + b2 + agg(h1@W2_bot)
// ---------------------------------------------------------------------------
extern "C" void kernel_launch(void* const* d_in, const int* in_sizes, int n_in,
                              void* d_out, int out_size) {
    const float* h   = (const float*)d_in[0];
    const float* W1  = (const float*)d_in[1];
    const float* b1  = (const float*)d_in[2];
    const float* W2  = (const float*)d_in[3];
    const float* b2  = (const float*)d_in[4];
    const int*   src = (const int*)d_in[5];
    const int*   dst = (const int*)d_in[6];
    float*       out = (float*)d_out;

    float *U, *V, *Y2, *P2;
    uint32_t *hPh, *hPl, *h1Ph, *h1Pl, *W1ph, *W1pl, *W2ph, *W2pl;
    cudaGetSymbolAddress((void**)&U,    g_U);
    cudaGetSymbolAddress((void**)&V,    g_V);
    cudaGetSymbolAddress((void**)&Y2,   g_Y2);
    cudaGetSymbolAddress((void**)&P2,   g_P2);
    cudaGetSymbolAddress((void**)&hPh,  g_hPh);
    cudaGetSymbolAddress((void**)&hPl,  g_hPl);
    cudaGetSymbolAddress((void**)&h1Ph, g_h1Ph);
    cudaGetSymbolAddress((void**)&h1Pl, g_h1Pl);
    cudaGetSymbolAddress((void**)&W1ph, g_W1ph);
    cudaGetSymbolAddress((void**)&W1pl, g_W1pl);
    cudaGetSymbolAddress((void**)&W2ph, g_W2ph);
    cudaGetSymbolAddress((void**)&W2pl, g_W2pl);

    cudaFuncSetAttribute(gemm1_kernel,
                         cudaFuncAttributeMaxDynamicSharedMemorySize, NT8_SMEM_BYTES);
    cudaFuncSetAttribute(gemm2_kernel,
                         cudaFuncAttributeMaxDynamicSharedMemorySize, NT8_SMEM_BYTES);

    const int MT = (N_NODES + 127) / 128;  // 79

    // 1: pack W1/W2/h + CSR count (fused)
    pack_all_kernel<<<dim3(77, 16), dim3(32, 8)>>>(W1, W2, h, dst);

    // 2: CSR scan
    scan_kernel<<<1, 1024>>>();

    // 3: GEMM1 -> U | V  with fused CSR fill (bx==8)
    {
        dim3 grid(9, MT);
        gemm1_kernel<<<grid, 256, NT8_SMEM_BYTES>>>(hPh, hPl, W1ph, W1pl, U, V,
                                                    N_NODES, src, dst);
    }

    // 4: h1 = relu(U + agg(V) + b1), packed   (profiled launch)
    agg_relu_pack_kernel<<<N_NODES, 128>>>(b1);

    // 5: dual GEMM2: Y2 = h1@W2_bot, P2 = h1@W2_top + b2
    {
        dim3 grid(2, MT);
        gemm2_kernel<<<grid, 256, NT8_SMEM_BYTES>>>(h1Ph, h1Pl, W2ph, W2pl, b2, Y2, P2, N_NODES);
    }

    // 6: out = P2 + agg(Y2); re-zero cnt/cur
    agg128_final_kernel<<<(N_NODES + 3) / 4, 128>>>(out);
}